// round 1
// baseline (speedup 1.0000x reference)
#include <cuda_runtime.h>

#define MAXN 50000
#define D 128
#define BM 64
#define BK 32

// Scratch (no cudaMalloc allowed)
__device__ float g_buf0[MAXN * D];   // aggregated input / normalized h1
__device__ float g_buf1[MAXN * D];   // GEMM outputs
__device__ float g_sum[2][D];
__device__ float g_sq[2][D];
__device__ float g_scale[2][D];
__device__ float g_shift[2][D];
__device__ int   g_is64;

// ---------------------------------------------------------------------------
// Detect whether edge_index is really int64 or int32 (JAX x64 ambiguity).
// If the buffer is int32 read as int64, values are (lo | hi<<32) with hi a
// random index in [0,N) -> out of range with prob ~1 per sample.
__global__ void detect_kernel(const long long* __restrict__ ei, int E, int N) {
    __shared__ int bad;
    if (threadIdx.x == 0) bad = 0;
    __syncthreads();
    int M = min(E, 4096);
    for (int i = threadIdx.x; i < M; i += blockDim.x) {
        long long v = ei[i];
        if (v < 0 || v >= (long long)N) bad = 1;
    }
    __syncthreads();
    if (threadIdx.x == 0) g_is64 = bad ? 0 : 1;
}

// ---------------------------------------------------------------------------
// out = (1+eps)*x ; also zero the stats accumulators
__global__ void init_kernel(const float* __restrict__ x,
                            const float* __restrict__ eps, int total4) {
    int i = blockIdx.x * blockDim.x + threadIdx.x;
    float s = 1.0f + eps[0];
    if (i < total4) {
        float4 v = ((const float4*)x)[i];
        v.x *= s; v.y *= s; v.z *= s; v.w *= s;
        ((float4*)g_buf0)[i] = v;
    }
    if (blockIdx.x == 0 && threadIdx.x < 2 * D) {
        int p = threadIdx.x / D, c = threadIdx.x % D;
        g_sum[p][c] = 0.f;
        g_sq[p][c]  = 0.f;
    }
}

// ---------------------------------------------------------------------------
// One warp per edge: gather x[src] row (32 x float4 = 128 floats),
// reduce-add into g_buf0[dst] with vector atomics.
__global__ void scatter_kernel(const float* __restrict__ x,
                               const void* __restrict__ ei_raw, int E) {
    int e = (blockIdx.x * blockDim.x + threadIdx.x) >> 5;
    if (e >= E) return;
    int lane = threadIdx.x & 31;
    long long s, d;
    if (g_is64) {
        const long long* p = (const long long*)ei_raw;
        s = p[e];
        d = p[E + e];
    } else {
        const int* p = (const int*)ei_raw;
        s = p[e];
        d = p[E + e];
    }
    float4 v = __ldg((const float4*)(x + s * D) + lane);
    float* addr = g_buf0 + d * D + (lane << 2);
    asm volatile("red.global.add.v4.f32 [%0], {%1,%2,%3,%4};"
                 :: "l"(addr), "f"(v.x), "f"(v.y), "f"(v.z), "f"(v.w)
                 : "memory");
}

// ---------------------------------------------------------------------------
// C[N,128] = g_buf0[N,128] @ W[128,128] + bias  -> g_buf1
// Tile: BM=64 rows x 128 cols, BK=32. 256 threads, each computes 4x8.
__global__ void __launch_bounds__(256) gemm_kernel(const float* __restrict__ W,
                                                   const float* __restrict__ bias,
                                                   int N) {
    __shared__ float As[BK][BM];      // transposed A tile
    __shared__ float Bs[BK][D];

    int tid = threadIdx.x;
    int tx = tid & 15;       // column group: cols tx*8 .. tx*8+7
    int ty = tid >> 4;       // row group:   rows ty + 16*i, i<4
    int rowStart = blockIdx.x * BM;

    float acc[4][8];
#pragma unroll
    for (int i = 0; i < 4; i++)
#pragma unroll
        for (int j = 0; j < 8; j++) acc[i][j] = 0.f;

    for (int kc = 0; kc < D; kc += BK) {
        // Load A tile (64x32 = 512 float4, 2 per thread), transpose into As
#pragma unroll
        for (int l = 0; l < 2; l++) {
            int t   = tid + 256 * l;
            int row = t >> 3;
            int c4  = t & 7;
            float4 v = make_float4(0.f, 0.f, 0.f, 0.f);
            int gr = rowStart + row;
            if (gr < N) v = ((const float4*)(g_buf0 + gr * D + kc))[c4];
            As[c4 * 4 + 0][row] = v.x;
            As[c4 * 4 + 1][row] = v.y;
            As[c4 * 4 + 2][row] = v.z;
            As[c4 * 4 + 3][row] = v.w;
        }
        // Load B tile (32x128 = 1024 float4 -> wait: 32*128/4 = 1024; 4 per thread)
#pragma unroll
        for (int l = 0; l < 4; l++) {
            int t   = tid + 256 * l;
            int row = t >> 5;
            int c4  = t & 31;
            float4 v = ((const float4*)(W + (kc + row) * D))[c4];
            *((float4*)&Bs[row][c4 * 4]) = v;
        }
        __syncthreads();

#pragma unroll
        for (int kk = 0; kk < BK; kk++) {
            float a[4];
#pragma unroll
            for (int i = 0; i < 4; i++) a[i] = As[kk][ty + 16 * i];
            float4 b0 = *((const float4*)&Bs[kk][tx * 8]);
            float4 b1 = *((const float4*)&Bs[kk][tx * 8 + 4]);
            float b[8] = {b0.x, b0.y, b0.z, b0.w, b1.x, b1.y, b1.z, b1.w};
#pragma unroll
            for (int i = 0; i < 4; i++)
#pragma unroll
                for (int j = 0; j < 8; j++) acc[i][j] += a[i] * b[j];
        }
        __syncthreads();
    }

    float4 bb0 = ((const float4*)bias)[tx * 2];
    float4 bb1 = ((const float4*)bias)[tx * 2 + 1];
#pragma unroll
    for (int i = 0; i < 4; i++) {
        int gr = rowStart + ty + 16 * i;
        if (gr < N) {
            float4 o0 = make_float4(acc[i][0] + bb0.x, acc[i][1] + bb0.y,
                                    acc[i][2] + bb0.z, acc[i][3] + bb0.w);
            float4 o1 = make_float4(acc[i][4] + bb1.x, acc[i][5] + bb1.y,
                                    acc[i][6] + bb1.z, acc[i][7] + bb1.w);
            float* out = g_buf1 + gr * D + tx * 8;
            *((float4*)out)       = o0;
            *((float4*)(out + 4)) = o1;
        }
    }
}

// ---------------------------------------------------------------------------
// Per-column sum / sum-of-squares over g_buf1, 128 rows per block.
__global__ void stats_kernel(int phase, int N) {
    int tid  = threadIdx.x;
    int c    = tid & 127;
    int half = tid >> 7;
    int rowStart = blockIdx.x * 128;
    float s = 0.f, q = 0.f;
    int rowEnd = min(rowStart + 128, N);
    for (int r = rowStart + half; r < rowEnd; r += 2) {
        float v = g_buf1[r * D + c];
        s += v;
        q += v * v;
    }
    __shared__ float sh[256], sh2[256];
    sh[tid]  = s;
    sh2[tid] = q;
    __syncthreads();
    if (half == 0) {
        atomicAdd(&g_sum[phase][c], sh[tid] + sh[tid + 128]);
        atomicAdd(&g_sq[phase][c],  sh2[tid] + sh2[tid + 128]);
    }
}

// ---------------------------------------------------------------------------
__global__ void finalize_kernel(int phase, const float* __restrict__ g,
                                const float* __restrict__ beta, float invN) {
    int c = threadIdx.x;
    float mu  = g_sum[phase][c] * invN;
    float var = g_sq[phase][c] * invN - mu * mu;
    float inv = rsqrtf(var + 1e-5f);
    float sc  = g[c] * inv;
    g_scale[phase][c] = sc;
    g_shift[phase][c] = beta[c] - mu * sc;
}

// ---------------------------------------------------------------------------
// relu(h*scale + shift); phase 0 -> g_buf0, phase 1 -> extout (d_out)
__global__ void norm_kernel(int phase, float* __restrict__ extout, int total4) {
    int i = blockIdx.x * blockDim.x + threadIdx.x;
    if (i >= total4) return;
    int c4 = i & 31;
    float4 v  = ((const float4*)g_buf1)[i];
    float4 sc = ((const float4*)g_scale[phase])[c4];
    float4 sh = ((const float4*)g_shift[phase])[c4];
    float4 o;
    o.x = fmaxf(v.x * sc.x + sh.x, 0.f);
    o.y = fmaxf(v.y * sc.y + sh.y, 0.f);
    o.z = fmaxf(v.z * sc.z + sh.z, 0.f);
    o.w = fmaxf(v.w * sc.w + sh.w, 0.f);
    float4* out = (phase == 0) ? (float4*)g_buf0 : (float4*)extout;
    out[i] = o;
}

// ---------------------------------------------------------------------------
extern "C" void kernel_launch(void* const* d_in, const int* in_sizes, int n_in,
                              void* d_out, int out_size) {
    const float* x   = (const float*)d_in[0];
    const void*  ei  = d_in[1];
    const float* eps = (const float*)d_in[2];
    const float* W1  = (const float*)d_in[3];
    const float* b1  = (const float*)d_in[4];
    const float* g1  = (const float*)d_in[5];
    const float* be1 = (const float*)d_in[6];
    const float* W2  = (const float*)d_in[7];
    const float* b2  = (const float*)d_in[8];
    const float* g2  = (const float*)d_in[9];
    const float* be2 = (const float*)d_in[10];

    int N = in_sizes[0] / D;
    int E = in_sizes[1] / 2;
    int total4 = N * (D / 4);
    const int TB = 256;

    detect_kernel<<<1, 256>>>((const long long*)ei, E, N);
    init_kernel<<<(total4 + TB - 1) / TB, TB>>>(x, eps, total4);

    long long sthreads = (long long)E * 32;
    scatter_kernel<<<(unsigned)((sthreads + TB - 1) / TB), TB>>>(x, ei, E);

    int gblocks = (N + BM - 1) / BM;
    int sblocks = (N + 127) / 128;
    float invN = 1.0f / (float)N;

    gemm_kernel<<<gblocks, 256>>>(W1, b1, N);
    stats_kernel<<<sblocks, 256>>>(0, N);
    finalize_kernel<<<1, D>>>(0, g1, be1, invN);
    norm_kernel<<<(total4 + TB - 1) / TB, TB>>>(0, nullptr, total4);

    gemm_kernel<<<gblocks, 256>>>(W2, b2, N);
    stats_kernel<<<sblocks, 256>>>(1, N);
    finalize_kernel<<<1, D>>>(1, g2, be2, invN);
    norm_kernel<<<(total4 + TB - 1) / TB, TB>>>(1, (float*)d_out, total4);
}